// round 2
// baseline (speedup 1.0000x reference)
#include <cuda_runtime.h>
#include <math.h>

#define CD 128
#define NMAX 100352
#define EMAX 1700000

// ---------------- device scratch ----------------
__device__ float g_P[(size_t)NMAX * CD];   // GEMM output / logits
__device__ float g_H[(size_t)NMAX * CD];   // hidden activations
__device__ float g_dis[NMAX];              // 1/sqrt(deg)
__device__ int   g_cnt[NMAX];              // incoming-edge counts (excl. self loop)
__device__ int   g_off[NMAX];              // exclusive prefix of counts
__device__ int   g_cur[NMAX];              // fill cursors
__device__ int   g_bkt[EMAX];              // bucketed source node ids
__device__ int   g_part[128];              // scan partials
__device__ float g_Wt[CD * CD];            // transposed weight (Wt[k][c])

// ---------------- f32x2 helpers ----------------
__device__ __forceinline__ void ffma2(unsigned long long& d,
                                      unsigned long long a,
                                      unsigned long long b) {
    asm("fma.rn.f32x2 %0, %1, %2, %0;" : "+l"(d) : "l"(a), "l"(b));
}
__device__ __forceinline__ unsigned long long dup2(float a) {
    unsigned long long r;
    unsigned int u = __float_as_uint(a);
    asm("mov.b64 %0, {%1, %1};" : "=l"(r) : "r"(u));
    return r;
}

// ---------------- small structural kernels ----------------
__global__ void k_zero_cnt(int n) {
    int i = blockIdx.x * blockDim.x + threadIdx.x;
    if (i < n) g_cnt[i] = 0;
}

__global__ void k_count(const int* __restrict__ col, int E) {
    for (int e = blockIdx.x * blockDim.x + threadIdx.x; e < E;
         e += gridDim.x * blockDim.x)
        atomicAdd(&g_cnt[col[e]], 1);
}

__global__ void k_dis(int n) {
    int i = blockIdx.x * blockDim.x + threadIdx.x;
    if (i < n) g_dis[i] = rsqrtf((float)g_cnt[i] + 1.0f);
}

// warp-shuffle scan, 1024/block: per-block exclusive scan + block sums.
__global__ void k_scan1(int n) {
    __shared__ int wsum[32];
    int tid = threadIdx.x;
    int lane = tid & 31, wid = tid >> 5;
    int i = blockIdx.x * 1024 + tid;
    int x = (i < n) ? g_cnt[i] : 0;
    int v = x;
#pragma unroll
    for (int d = 1; d < 32; d <<= 1) {
        int t = __shfl_up_sync(0xFFFFFFFFu, v, d);
        if (lane >= d) v += t;
    }
    if (lane == 31) wsum[wid] = v;
    __syncthreads();
    if (wid == 0) {
        int w = wsum[lane];
#pragma unroll
        for (int d = 1; d < 32; d <<= 1) {
            int t = __shfl_up_sync(0xFFFFFFFFu, w, d);
            if (lane >= d) w += t;
        }
        wsum[lane] = w;
    }
    __syncthreads();
    int base = (wid > 0) ? wsum[wid - 1] : 0;
    if (i < n) g_off[i] = base + v - x;            // exclusive within block
    if (tid == 1023) g_part[blockIdx.x] = wsum[31];
}

__global__ void k_scan2(int nb) {   // single block of 128 threads, nb <= 128
    __shared__ int s[128];
    int tid = threadIdx.x;
    int x = (tid < nb) ? g_part[tid] : 0;
    s[tid] = x;
    __syncthreads();
    for (int d = 1; d < 128; d <<= 1) {
        int t = (tid >= d) ? s[tid - d] : 0;
        __syncthreads();
        s[tid] += t;
        __syncthreads();
    }
    if (tid < nb) g_part[tid] = s[tid] - x;      // exclusive
}

__global__ void k_scan3(int n) {
    int i = blockIdx.x * blockDim.x + threadIdx.x;
    if (i < n) {
        int v = g_off[i] + g_part[i >> 10];
        g_off[i] = v;
        g_cur[i] = v;
    }
}

__global__ void k_fill(const int* __restrict__ row, const int* __restrict__ col, int E) {
    for (int e = blockIdx.x * blockDim.x + threadIdx.x; e < E;
         e += gridDim.x * blockDim.x) {
        int p = atomicAdd(&g_cur[col[e]], 1);
        g_bkt[p] = row[e];
    }
}

__global__ void k_transpose(const float* __restrict__ W) {
    int i = blockIdx.x * 256 + threadIdx.x;   // 64 blocks * 256 = 16384 = 128*128
    int c = i >> 7, k = i & 127;
    g_Wt[k * CD + c] = W[i];                  // W[c][k] -> Wt[k][c]
}

// ---------------- GEMM: P[i][c] = (dis[i])? * sum_k X[i][k] * Wt[k][c] ----------------
// 128x128 tile per block, 256 threads, 8x8 micro-tile via packed f32x2 FMA.
__global__ void __launch_bounds__(256, 2)
k_gemm(const float* __restrict__ Xext, int useExt, int useDis, int n) {
    __shared__ float Xs[128][36];   // [row][k], padded
    __shared__ float Ws[32][128];   // [k][col]
    const float* __restrict__ X = useExt ? Xext : g_H;

    int row0 = blockIdx.x * 128;
    int tid = threadIdx.x;
    int tx = tid & 15, ty = tid >> 4;

    // packed accumulators: acc2[i][j] = {col 2j, col 2j+1} within the two
    // 4-column groups (tx*4.. and 64+tx*4..)
    unsigned long long acc2[8][4];
#pragma unroll
    for (int i = 0; i < 8; i++)
#pragma unroll
        for (int j = 0; j < 4; j++) acc2[i][j] = 0ull;

    for (int kc = 0; kc < 128; kc += 32) {
#pragma unroll
        for (int p = 0; p < 4; p++) {        // load X tile 128x32 (float4)
            int f = tid + p * 256;
            int r = f >> 3, c4 = f & 7;
            float4 v = make_float4(0.f, 0.f, 0.f, 0.f);
            int gr = row0 + r;
            if (gr < n) v = *(const float4*)&X[(size_t)gr * CD + kc + c4 * 4];
            Xs[r][c4 * 4 + 0] = v.x;
            Xs[r][c4 * 4 + 1] = v.y;
            Xs[r][c4 * 4 + 2] = v.z;
            Xs[r][c4 * 4 + 3] = v.w;
        }
#pragma unroll
        for (int p = 0; p < 4; p++) {        // load W tile 32x128 (float4)
            int f = tid + p * 256;
            int k = f >> 5, c4 = f & 31;
            *(float4*)&Ws[k][c4 * 4] = *(const float4*)&g_Wt[(size_t)(kc + k) * CD + c4 * 4];
        }
        __syncthreads();

#pragma unroll 4
        for (int k = 0; k < 32; k++) {
            unsigned long long ad[8];
#pragma unroll
            for (int i = 0; i < 4; i++) {
                ad[i]     = dup2(Xs[ty * 4 + i][k]);
                ad[4 + i] = dup2(Xs[64 + ty * 4 + i][k]);
            }
            unsigned long long b2[4];
            b2[0] = *(const unsigned long long*)&Ws[k][tx * 4];
            b2[1] = *(const unsigned long long*)&Ws[k][tx * 4 + 2];
            b2[2] = *(const unsigned long long*)&Ws[k][64 + tx * 4];
            b2[3] = *(const unsigned long long*)&Ws[k][64 + tx * 4 + 2];
#pragma unroll
            for (int i = 0; i < 8; i++) {
#pragma unroll
                for (int j = 0; j < 4; j++) ffma2(acc2[i][j], ad[i], b2[j]);
            }
        }
        __syncthreads();
    }

#pragma unroll
    for (int i = 0; i < 8; i++) {
        int r = (i < 4) ? (ty * 4 + i) : (64 + ty * 4 + i - 4);
        int gr = row0 + r;
        if (gr < n) {
            float s = useDis ? g_dis[gr] : 1.0f;
            union { unsigned long long u; float2 f; } c0, c1, c2, c3;
            c0.u = acc2[i][0]; c1.u = acc2[i][1];
            c2.u = acc2[i][2]; c3.u = acc2[i][3];
            float4 o0 = make_float4(c0.f.x * s, c0.f.y * s, c1.f.x * s, c1.f.y * s);
            float4 o1 = make_float4(c2.f.x * s, c2.f.y * s, c3.f.x * s, c3.f.y * s);
            *(float4*)&g_P[(size_t)gr * CD + tx * 4] = o0;
            *(float4*)&g_P[(size_t)gr * CD + 64 + tx * 4] = o1;
        }
    }
}

// ---------------- gather: H[i] = relu(dis[i]*(P[i] + sum_{j->i} P[j]) + b) ----------------
__global__ void k_gather(const float* __restrict__ bias, int n) {
    int w = (blockIdx.x * blockDim.x + threadIdx.x) >> 5;
    if (w >= n) return;
    int lane = threadIdx.x & 31;

    const float4* __restrict__ P4 = (const float4*)g_P;
    float4 acc = P4[(size_t)w * 32 + lane];          // self loop
    int o = g_off[w];
    int c = g_cnt[w];

    int j = 0;
    for (; j + 2 <= c; j += 2) {
        int r0 = g_bkt[o + j];
        int r1 = g_bkt[o + j + 1];
        float4 v0 = P4[(size_t)r0 * 32 + lane];
        float4 v1 = P4[(size_t)r1 * 32 + lane];
        acc.x += v0.x; acc.y += v0.y; acc.z += v0.z; acc.w += v0.w;
        acc.x += v1.x; acc.y += v1.y; acc.z += v1.z; acc.w += v1.w;
    }
    if (j < c) {
        int r0 = g_bkt[o + j];
        float4 v0 = P4[(size_t)r0 * 32 + lane];
        acc.x += v0.x; acc.y += v0.y; acc.z += v0.z; acc.w += v0.w;
    }

    float s = g_dis[w];
    float4 b = *(const float4*)&bias[lane * 4];
    float4 out;
    out.x = fmaxf(fmaf(acc.x, s, b.x), 0.0f);
    out.y = fmaxf(fmaf(acc.y, s, b.y), 0.0f);
    out.z = fmaxf(fmaf(acc.z, s, b.z), 0.0f);
    out.w = fmaxf(fmaf(acc.w, s, b.w), 0.0f);
    ((float4*)g_H)[(size_t)w * 32 + lane] = out;
}

// ---------------- log_softmax over 128 classes, one warp per row ----------------
__global__ void k_logsoftmax(const float* __restrict__ bl, float* __restrict__ out, int n) {
    int w = (blockIdx.x * blockDim.x + threadIdx.x) >> 5;
    if (w >= n) return;
    int lane = threadIdx.x & 31;

    float4 v = *(const float4*)&g_P[(size_t)w * CD + lane * 4];
    float4 b = *(const float4*)&bl[lane * 4];
    v.x += b.x; v.y += b.y; v.z += b.z; v.w += b.w;

    float m = fmaxf(fmaxf(v.x, v.y), fmaxf(v.z, v.w));
#pragma unroll
    for (int d = 16; d; d >>= 1) m = fmaxf(m, __shfl_xor_sync(0xFFFFFFFFu, m, d));

    float s = expf(v.x - m) + expf(v.y - m) + expf(v.z - m) + expf(v.w - m);
#pragma unroll
    for (int d = 16; d; d >>= 1) s += __shfl_xor_sync(0xFFFFFFFFu, s, d);

    float l = m + logf(s);
    float4 o = make_float4(v.x - l, v.y - l, v.z - l, v.w - l);
    *(float4*)&out[(size_t)w * CD + lane * 4] = o;
}

// ---------------- launch ----------------
extern "C" void kernel_launch(void* const* d_in, const int* in_sizes, int n_in,
                              void* d_out, int out_size) {
    const float* x  = (const float*)d_in[0];
    const int*   ei = (const int*)d_in[1];
    const float* b1 = (const float*)d_in[3];
    const float* b2 = (const float*)d_in[5];
    const float* bl = (const float*)d_in[7];
    const float* W1 = (const float*)d_in[2];
    const float* W2 = (const float*)d_in[4];
    const float* Wl = (const float*)d_in[6];

    int n = in_sizes[0] / CD;
    int E = in_sizes[1] / 2;
    const int* row = ei;
    const int* col = ei + E;

    int nb256 = (n + 255) / 256;
    int nbScan = (n + 1023) / 1024;
    int gatherB = (n + 7) / 8;       // (n warps * 32) / 256
    int gemmB = (n + 127) / 128;

    // degree + bucketing (shared by both convs)
    k_zero_cnt<<<nb256, 256>>>(n);
    k_count<<<2048, 256>>>(col, E);
    k_dis<<<nb256, 256>>>(n);
    k_scan1<<<nbScan, 1024>>>(n);
    k_scan2<<<1, 128>>>(nbScan);
    k_scan3<<<nb256, 256>>>(n);
    k_fill<<<2048, 256>>>(row, col, E);

    // conv1
    k_transpose<<<64, 256>>>(W1);
    k_gemm<<<gemmB, 256>>>(x, 1, 1, n);
    k_gather<<<gatherB, 256>>>(b1, n);

    // conv2
    k_transpose<<<64, 256>>>(W2);
    k_gemm<<<gemmB, 256>>>(nullptr, 0, 1, n);
    k_gather<<<gatherB, 256>>>(b2, n);

    // linear + log_softmax
    k_transpose<<<64, 256>>>(Wl);
    k_gemm<<<gemmB, 256>>>(nullptr, 0, 0, n);
    k_logsoftmax<<<gatherB, 256>>>(bl, (float*)d_out, n);
}

// round 3
// speedup vs baseline: 1.5091x; 1.5091x over previous
#include <cuda_runtime.h>
#include <math.h>

#define CD 128
#define NMAX 100352
#define EMAX 1700000

// ---------------- device scratch ----------------
__device__ float g_P[(size_t)NMAX * CD];   // GEMM output / logits
__device__ float g_H[(size_t)NMAX * CD];   // hidden activations (tf32-rounded)
__device__ float g_dis[NMAX];              // 1/sqrt(deg)
__device__ int   g_cnt[NMAX];              // incoming-edge counts (excl. self loop)
__device__ int   g_off[NMAX];              // exclusive prefix of counts
__device__ int   g_cur[NMAX];              // fill cursors
__device__ int   g_bkt[EMAX];              // bucketed source node ids
__device__ int   g_part[128];              // scan partials
__device__ float g_Wt[CD * CD];            // transposed weight (tf32-rounded)

// ---------------- helpers ----------------
__device__ __forceinline__ unsigned int tf32r(float x) {
    unsigned int r;
    asm("cvt.rna.tf32.f32 %0, %1;" : "=r"(r) : "f"(x));
    return r;
}
__device__ __forceinline__ float tf32rf(float x) {
    return __uint_as_float(tf32r(x));
}

// ---------------- small structural kernels ----------------
__global__ void k_zero_cnt(int n) {
    int i = blockIdx.x * blockDim.x + threadIdx.x;
    if (i < n) g_cnt[i] = 0;
}

__global__ void k_count(const int* __restrict__ col, int E) {
    for (int e = blockIdx.x * blockDim.x + threadIdx.x; e < E;
         e += gridDim.x * blockDim.x)
        atomicAdd(&g_cnt[col[e]], 1);
}

__global__ void k_dis(int n) {
    int i = blockIdx.x * blockDim.x + threadIdx.x;
    if (i < n) g_dis[i] = rsqrtf((float)g_cnt[i] + 1.0f);
}

// warp-shuffle scan, 1024/block
__global__ void k_scan1(int n) {
    __shared__ int wsum[32];
    int tid = threadIdx.x;
    int lane = tid & 31, wid = tid >> 5;
    int i = blockIdx.x * 1024 + tid;
    int x = (i < n) ? g_cnt[i] : 0;
    int v = x;
#pragma unroll
    for (int d = 1; d < 32; d <<= 1) {
        int t = __shfl_up_sync(0xFFFFFFFFu, v, d);
        if (lane >= d) v += t;
    }
    if (lane == 31) wsum[wid] = v;
    __syncthreads();
    if (wid == 0) {
        int w = wsum[lane];
#pragma unroll
        for (int d = 1; d < 32; d <<= 1) {
            int t = __shfl_up_sync(0xFFFFFFFFu, w, d);
            if (lane >= d) w += t;
        }
        wsum[lane] = w;
    }
    __syncthreads();
    int base = (wid > 0) ? wsum[wid - 1] : 0;
    if (i < n) g_off[i] = base + v - x;
    if (tid == 1023) g_part[blockIdx.x] = wsum[31];
}

__global__ void k_scan2(int nb) {
    __shared__ int s[128];
    int tid = threadIdx.x;
    int x = (tid < nb) ? g_part[tid] : 0;
    s[tid] = x;
    __syncthreads();
    for (int d = 1; d < 128; d <<= 1) {
        int t = (tid >= d) ? s[tid - d] : 0;
        __syncthreads();
        s[tid] += t;
        __syncthreads();
    }
    if (tid < nb) g_part[tid] = s[tid] - x;
}

__global__ void k_scan3(int n) {
    int i = blockIdx.x * blockDim.x + threadIdx.x;
    if (i < n) {
        int v = g_off[i] + g_part[i >> 10];
        g_off[i] = v;
        g_cur[i] = v;
    }
}

__global__ void k_fill(const int* __restrict__ row, const int* __restrict__ col, int E) {
    for (int e = blockIdx.x * blockDim.x + threadIdx.x; e < E;
         e += gridDim.x * blockDim.x) {
        int p = atomicAdd(&g_cur[col[e]], 1);
        g_bkt[p] = row[e];
    }
}

__global__ void k_transpose(const float* __restrict__ W) {
    int i = blockIdx.x * 256 + threadIdx.x;
    int c = i >> 7, k = i & 127;
    g_Wt[k * CD + c] = tf32rf(W[i]);          // W[c][k] -> Wt[k][c], tf32-rounded
}

// ---------------- tensor-core GEMM: P[i][c] = dis? * sum_k X[i][k] * Wt[k][c] ----------
// 128x128 tile / block, 256 thr (8 warps = 2m x 4n), warp tile 64x32 = 4x4 m16n8k8 mmas.
__global__ void __launch_bounds__(256)
k_gemm_tc(const float* __restrict__ Xext, int useExt, int useDis, int doCvt, int n) {
    __shared__ float Xs[128][36];    // [row][k] pad->A-frag reads conflict-free
    __shared__ float Ws[32][136];    // [k][col] pad->B-frag reads conflict-free
    const float* __restrict__ X = useExt ? Xext : g_H;

    int row0 = blockIdx.x * 128;
    int tid = threadIdx.x;
    int wid = tid >> 5, lane = tid & 31;
    int gid = lane >> 2, tig = lane & 3;
    int wm = wid >> 2, wn = wid & 3;          // warp grid 2x4
    int mbase = wm * 64, nbase = wn * 32;

    float acc[4][4][4];
#pragma unroll
    for (int a = 0; a < 4; a++)
#pragma unroll
        for (int b = 0; b < 4; b++)
#pragma unroll
            for (int c = 0; c < 4; c++) acc[a][b][c] = 0.0f;

    for (int kc = 0; kc < 128; kc += 32) {
#pragma unroll
        for (int p = 0; p < 4; p++) {         // X tile 128x32
            int f = tid + p * 256;
            int r = f >> 3, c4 = f & 7;
            float4 v = make_float4(0.f, 0.f, 0.f, 0.f);
            int gr = row0 + r;
            if (gr < n) v = *(const float4*)&X[(size_t)gr * CD + kc + c4 * 4];
            if (doCvt) { v.x = tf32rf(v.x); v.y = tf32rf(v.y);
                         v.z = tf32rf(v.z); v.w = tf32rf(v.w); }
            Xs[r][c4 * 4 + 0] = v.x; Xs[r][c4 * 4 + 1] = v.y;
            Xs[r][c4 * 4 + 2] = v.z; Xs[r][c4 * 4 + 3] = v.w;
        }
#pragma unroll
        for (int p = 0; p < 4; p++) {         // W tile 32x128 (pre-rounded)
            int f = tid + p * 256;
            int k = f >> 5, c4 = f & 31;
            *(float4*)&Ws[k][c4 * 4] = *(const float4*)&g_Wt[(size_t)(kc + k) * CD + c4 * 4];
        }
        __syncthreads();

#pragma unroll
        for (int kb = 0; kb < 32; kb += 8) {
            unsigned int af[4][4];
#pragma unroll
            for (int mt = 0; mt < 4; mt++) {
                int r = mbase + mt * 16 + gid;
                af[mt][0] = __float_as_uint(Xs[r][kb + tig]);
                af[mt][1] = __float_as_uint(Xs[r + 8][kb + tig]);
                af[mt][2] = __float_as_uint(Xs[r][kb + tig + 4]);
                af[mt][3] = __float_as_uint(Xs[r + 8][kb + tig + 4]);
            }
            unsigned int bf[4][2];
#pragma unroll
            for (int nt = 0; nt < 4; nt++) {
                int cn = nbase + nt * 8 + gid;
                bf[nt][0] = __float_as_uint(Ws[kb + tig][cn]);
                bf[nt][1] = __float_as_uint(Ws[kb + tig + 4][cn]);
            }
#pragma unroll
            for (int mt = 0; mt < 4; mt++)
#pragma unroll
                for (int nt = 0; nt < 4; nt++) {
                    asm("mma.sync.aligned.m16n8k8.row.col.f32.tf32.tf32.f32 "
                        "{%0,%1,%2,%3}, {%4,%5,%6,%7}, {%8,%9}, {%0,%1,%2,%3};"
                        : "+f"(acc[mt][nt][0]), "+f"(acc[mt][nt][1]),
                          "+f"(acc[mt][nt][2]), "+f"(acc[mt][nt][3])
                        : "r"(af[mt][0]), "r"(af[mt][1]), "r"(af[mt][2]), "r"(af[mt][3]),
                          "r"(bf[nt][0]), "r"(bf[nt][1]));
                }
        }
        __syncthreads();
    }

    // epilogue: d[r][c]: c0/c1 at row gid, c2/c3 at row gid+8, cols 2*tig, 2*tig+1
#pragma unroll
    for (int mt = 0; mt < 4; mt++) {
        int r0 = row0 + mbase + mt * 16 + gid;
        int r1 = r0 + 8;
        float s0 = 1.0f, s1 = 1.0f;
        if (r0 < n && useDis) s0 = g_dis[r0];
        if (r1 < n && useDis) s1 = g_dis[r1];
#pragma unroll
        for (int nt = 0; nt < 4; nt++) {
            int cn = nbase + nt * 8 + tig * 2;
            if (r0 < n) {
                float2 o = make_float2(acc[mt][nt][0] * s0, acc[mt][nt][1] * s0);
                *(float2*)&g_P[(size_t)r0 * CD + cn] = o;
            }
            if (r1 < n) {
                float2 o = make_float2(acc[mt][nt][2] * s1, acc[mt][nt][3] * s1);
                *(float2*)&g_P[(size_t)r1 * CD + cn] = o;
            }
        }
    }
}

// ---------------- gather: H[i] = tf32(relu(dis[i]*(P[i] + sum_{j->i} P[j]) + b)) -------
__global__ void k_gather(const float* __restrict__ bias, int n) {
    int w = (blockIdx.x * blockDim.x + threadIdx.x) >> 5;
    if (w >= n) return;
    int lane = threadIdx.x & 31;

    const float4* __restrict__ P4 = (const float4*)g_P;
    float4 acc = P4[(size_t)w * 32 + lane];          // self loop
    int o = g_off[w];
    int c = g_cnt[w];

    int j = 0;
    for (; j + 2 <= c; j += 2) {
        int r0 = g_bkt[o + j];
        int r1 = g_bkt[o + j + 1];
        float4 v0 = P4[(size_t)r0 * 32 + lane];
        float4 v1 = P4[(size_t)r1 * 32 + lane];
        acc.x += v0.x; acc.y += v0.y; acc.z += v0.z; acc.w += v0.w;
        acc.x += v1.x; acc.y += v1.y; acc.z += v1.z; acc.w += v1.w;
    }
    if (j < c) {
        int r0 = g_bkt[o + j];
        float4 v0 = P4[(size_t)r0 * 32 + lane];
        acc.x += v0.x; acc.y += v0.y; acc.z += v0.z; acc.w += v0.w;
    }

    float s = g_dis[w];
    float4 b = *(const float4*)&bias[lane * 4];
    float4 out;
    out.x = tf32rf(fmaxf(fmaf(acc.x, s, b.x), 0.0f));
    out.y = tf32rf(fmaxf(fmaf(acc.y, s, b.y), 0.0f));
    out.z = tf32rf(fmaxf(fmaf(acc.z, s, b.z), 0.0f));
    out.w = tf32rf(fmaxf(fmaf(acc.w, s, b.w), 0.0f));
    ((float4*)g_H)[(size_t)w * 32 + lane] = out;
}

// ---------------- log_softmax over 128 classes, one warp per row ----------------
__global__ void k_logsoftmax(const float* __restrict__ bl, float* __restrict__ out, int n) {
    int w = (blockIdx.x * blockDim.x + threadIdx.x) >> 5;
    if (w >= n) return;
    int lane = threadIdx.x & 31;

    float4 v = *(const float4*)&g_P[(size_t)w * CD + lane * 4];
    float4 b = *(const float4*)&bl[lane * 4];
    v.x += b.x; v.y += b.y; v.z += b.z; v.w += b.w;

    float m = fmaxf(fmaxf(v.x, v.y), fmaxf(v.z, v.w));
#pragma unroll
    for (int d = 16; d; d >>= 1) m = fmaxf(m, __shfl_xor_sync(0xFFFFFFFFu, m, d));

    float s = expf(v.x - m) + expf(v.y - m) + expf(v.z - m) + expf(v.w - m);
#pragma unroll
    for (int d = 16; d; d >>= 1) s += __shfl_xor_sync(0xFFFFFFFFu, s, d);

    float l = m + logf(s);
    float4 o = make_float4(v.x - l, v.y - l, v.z - l, v.w - l);
    *(float4*)&out[(size_t)w * CD + lane * 4] = o;
}

// ---------------- launch ----------------
extern "C" void kernel_launch(void* const* d_in, const int* in_sizes, int n_in,
                              void* d_out, int out_size) {
    const float* x  = (const float*)d_in[0];
    const int*   ei = (const int*)d_in[1];
    const float* b1 = (const float*)d_in[3];
    const float* b2 = (const float*)d_in[5];
    const float* bl = (const float*)d_in[7];
    const float* W1 = (const float*)d_in[2];
    const float* W2 = (const float*)d_in[4];
    const float* Wl = (const float*)d_in[6];

    int n = in_sizes[0] / CD;
    int E = in_sizes[1] / 2;
    const int* row = ei;
    const int* col = ei + E;

    int nb256 = (n + 255) / 256;
    int nbScan = (n + 1023) / 1024;
    int gatherB = (n + 7) / 8;
    int gemmB = (n + 127) / 128;

    // degree + bucketing (shared by both convs)
    k_zero_cnt<<<nb256, 256>>>(n);
    k_count<<<2048, 256>>>(col, E);
    k_dis<<<nb256, 256>>>(n);
    k_scan1<<<nbScan, 1024>>>(n);
    k_scan2<<<1, 128>>>(nbScan);
    k_scan3<<<nb256, 256>>>(n);
    k_fill<<<2048, 256>>>(row, col, E);

    // conv1
    k_transpose<<<64, 256>>>(W1);
    k_gemm_tc<<<gemmB, 256>>>(x, 1, 1, 1, n);
    k_gather<<<gatherB, 256>>>(b1, n);

    // conv2
    k_transpose<<<64, 256>>>(W2);
    k_gemm_tc<<<gemmB, 256>>>(nullptr, 0, 1, 0, n);
    k_gather<<<gatherB, 256>>>(b2, n);

    // linear + log_softmax
    k_transpose<<<64, 256>>>(Wl);
    k_gemm_tc<<<gemmB, 256>>>(nullptr, 0, 0, 0, n);
    k_logsoftmax<<<gatherB, 256>>>(bl, (float*)d_out, n);
}

// round 4
// speedup vs baseline: 1.8694x; 1.2387x over previous
#include <cuda_runtime.h>
#include <cuda_bf16.h>
#include <math.h>

#define CD 128
#define NMAX 100352
#define EMAX 1700000

// ---------------- device scratch ----------------
__device__ __align__(16) float g_P[(size_t)NMAX * CD];  // fp32 logits OR bf16 conv out (cast)
__device__ __align__(16) float g_H[(size_t)NMAX * CD / 2]; // bf16 hidden (cast)
__device__ float g_dis[NMAX];
__device__ int   g_cnt[NMAX];
__device__ int   g_off[NMAX];
__device__ int   g_cur[NMAX];
__device__ int   g_bkt[EMAX];
__device__ int   g_part[128];
__device__ __align__(16) __nv_bfloat16 g_Wb[CD * CD];   // bf16 W[c_out][c_in] (k contiguous)

__device__ __forceinline__ unsigned int pack_bf16x2(float lo, float hi) {
    unsigned int r;
    asm("cvt.rn.bf16x2.f32 %0, %1, %2;" : "=r"(r) : "f"(hi), "f"(lo));
    return r;
}

// ---------------- small structural kernels ----------------
__global__ void k_zero_cnt(int n) {
    int i = blockIdx.x * blockDim.x + threadIdx.x;
    if (i < n) g_cnt[i] = 0;
}

__global__ void k_count(const int* __restrict__ col, int E) {
    for (int e = blockIdx.x * blockDim.x + threadIdx.x; e < E;
         e += gridDim.x * blockDim.x)
        atomicAdd(&g_cnt[col[e]], 1);
}

__global__ void k_dis(int n) {
    int i = blockIdx.x * blockDim.x + threadIdx.x;
    if (i < n) g_dis[i] = rsqrtf((float)g_cnt[i] + 1.0f);
}

__global__ void k_scan1(int n) {
    __shared__ int wsum[32];
    int tid = threadIdx.x;
    int lane = tid & 31, wid = tid >> 5;
    int i = blockIdx.x * 1024 + tid;
    int x = (i < n) ? g_cnt[i] : 0;
    int v = x;
#pragma unroll
    for (int d = 1; d < 32; d <<= 1) {
        int t = __shfl_up_sync(0xFFFFFFFFu, v, d);
        if (lane >= d) v += t;
    }
    if (lane == 31) wsum[wid] = v;
    __syncthreads();
    if (wid == 0) {
        int w = wsum[lane];
#pragma unroll
        for (int d = 1; d < 32; d <<= 1) {
            int t = __shfl_up_sync(0xFFFFFFFFu, w, d);
            if (lane >= d) w += t;
        }
        wsum[lane] = w;
    }
    __syncthreads();
    int base = (wid > 0) ? wsum[wid - 1] : 0;
    if (i < n) g_off[i] = base + v - x;
    if (tid == 1023) g_part[blockIdx.x] = wsum[31];
}

__global__ void k_scan2(int nb) {
    __shared__ int s[128];
    int tid = threadIdx.x;
    int x = (tid < nb) ? g_part[tid] : 0;
    s[tid] = x;
    __syncthreads();
    for (int d = 1; d < 128; d <<= 1) {
        int t = (tid >= d) ? s[tid - d] : 0;
        __syncthreads();
        s[tid] += t;
        __syncthreads();
    }
    if (tid < nb) g_part[tid] = s[tid] - x;
}

__global__ void k_scan3(int n) {
    int i = blockIdx.x * blockDim.x + threadIdx.x;
    if (i < n) {
        int v = g_off[i] + g_part[i >> 10];
        g_off[i] = v;
        g_cur[i] = v;
    }
}

__global__ void k_fill(const int* __restrict__ row, const int* __restrict__ col, int E) {
    for (int e = blockIdx.x * blockDim.x + threadIdx.x; e < E;
         e += gridDim.x * blockDim.x) {
        int p = atomicAdd(&g_cur[col[e]], 1);
        g_bkt[p] = row[e];
    }
}

__global__ void k_cvtW(const float* __restrict__ W) {
    int i = blockIdx.x * 256 + threadIdx.x;   // 64 * 256 = 16384
    g_Wb[i] = __float2bfloat16(W[i]);         // keep W[c][k] layout, k contiguous
}

// ---------------- bf16 tensor-core GEMM --------------------------------------------
// P[i][c] = dis? * sum_k X[i][k] * W[c][k]; 128x128 tile, 256 thr, m16n8k16 bf16 MMA.
__global__ void __launch_bounds__(256)
k_gemm_bf16(const float* __restrict__ Xf, int useXf, int useDis, int outF32, int n) {
    __shared__ __align__(16) __nv_bfloat16 Xs[128][72];   // [row][k], pad 8
    __shared__ __align__(16) __nv_bfloat16 Ws[128][72];   // [c_out][k], pad 8

    const __nv_bfloat16* __restrict__ Hb = (const __nv_bfloat16*)g_H;

    int row0 = blockIdx.x * 128;
    int tid = threadIdx.x;
    int wid = tid >> 5, lane = tid & 31;
    int gid = lane >> 2, tig = lane & 3;
    int wm = wid >> 2, wn = wid & 3;            // 2x4 warp grid
    int mbase = wm * 64, nbase = wn * 32;

    float acc[4][4][4];
#pragma unroll
    for (int a = 0; a < 4; a++)
#pragma unroll
        for (int b = 0; b < 4; b++)
#pragma unroll
            for (int c = 0; c < 4; c++) acc[a][b][c] = 0.0f;

    for (int kc = 0; kc < 128; kc += 64) {
        if (useXf) {
            // X fp32 -> bf16 tile: 128 rows x 64 cols, float4 per thread x8
#pragma unroll
            for (int p = 0; p < 8; p++) {
                int f = tid + p * 256;
                int r = f >> 4, c4 = f & 15;
                float4 v = make_float4(0.f, 0.f, 0.f, 0.f);
                int gr = row0 + r;
                if (gr < n) v = *(const float4*)&Xf[(size_t)gr * CD + kc + c4 * 4];
                unsigned int u0 = pack_bf16x2(v.x, v.y);
                unsigned int u1 = pack_bf16x2(v.z, v.w);
                *(uint2*)&Xs[r][c4 * 4] = make_uint2(u0, u1);
            }
        } else {
            // H bf16 tile: uint4 = 8 bf16 per thread x4
#pragma unroll
            for (int p = 0; p < 4; p++) {
                int f = tid + p * 256;
                int r = f >> 3, c8 = f & 7;
                uint4 v = make_uint4(0, 0, 0, 0);
                int gr = row0 + r;
                if (gr < n) v = *(const uint4*)&Hb[(size_t)gr * CD + kc + c8 * 8];
                *(uint4*)&Xs[r][c8 * 8] = v;
            }
        }
#pragma unroll
        for (int p = 0; p < 4; p++) {           // W tile 128 x 64 bf16
            int f = tid + p * 256;
            int r = f >> 3, c8 = f & 7;
            *(uint4*)&Ws[r][c8 * 8] = *(const uint4*)&g_Wb[(size_t)r * CD + kc + c8 * 8];
        }
        __syncthreads();

#pragma unroll
        for (int kb = 0; kb < 64; kb += 16) {
            unsigned int af[4][4];
#pragma unroll
            for (int mt = 0; mt < 4; mt++) {
                int r = mbase + mt * 16 + gid;
                af[mt][0] = *(const unsigned int*)&Xs[r][kb + 2 * tig];
                af[mt][1] = *(const unsigned int*)&Xs[r + 8][kb + 2 * tig];
                af[mt][2] = *(const unsigned int*)&Xs[r][kb + 2 * tig + 8];
                af[mt][3] = *(const unsigned int*)&Xs[r + 8][kb + 2 * tig + 8];
            }
            unsigned int bf[4][2];
#pragma unroll
            for (int nt = 0; nt < 4; nt++) {
                int cn = nbase + nt * 8 + gid;
                bf[nt][0] = *(const unsigned int*)&Ws[cn][kb + 2 * tig];
                bf[nt][1] = *(const unsigned int*)&Ws[cn][kb + 2 * tig + 8];
            }
#pragma unroll
            for (int mt = 0; mt < 4; mt++)
#pragma unroll
                for (int nt = 0; nt < 4; nt++) {
                    asm("mma.sync.aligned.m16n8k16.row.col.f32.bf16.bf16.f32 "
                        "{%0,%1,%2,%3}, {%4,%5,%6,%7}, {%8,%9}, {%0,%1,%2,%3};"
                        : "+f"(acc[mt][nt][0]), "+f"(acc[mt][nt][1]),
                          "+f"(acc[mt][nt][2]), "+f"(acc[mt][nt][3])
                        : "r"(af[mt][0]), "r"(af[mt][1]), "r"(af[mt][2]), "r"(af[mt][3]),
                          "r"(bf[nt][0]), "r"(bf[nt][1]));
                }
        }
        __syncthreads();
    }

    // epilogue: c0/c1 at row gid cols 2tig,2tig+1; c2/c3 at row gid+8
    __nv_bfloat16* Pb = (__nv_bfloat16*)g_P;
#pragma unroll
    for (int mt = 0; mt < 4; mt++) {
        int r0 = row0 + mbase + mt * 16 + gid;
        int r1 = r0 + 8;
        float s0 = (r0 < n && useDis) ? g_dis[r0] : 1.0f;
        float s1 = (r1 < n && useDis) ? g_dis[r1] : 1.0f;
#pragma unroll
        for (int nt = 0; nt < 4; nt++) {
            int cn = nbase + nt * 8 + tig * 2;
            if (outF32) {
                if (r0 < n)
                    *(float2*)&g_P[(size_t)r0 * CD + cn] =
                        make_float2(acc[mt][nt][0] * s0, acc[mt][nt][1] * s0);
                if (r1 < n)
                    *(float2*)&g_P[(size_t)r1 * CD + cn] =
                        make_float2(acc[mt][nt][2] * s1, acc[mt][nt][3] * s1);
            } else {
                if (r0 < n)
                    *(unsigned int*)&Pb[(size_t)r0 * CD + cn] =
                        pack_bf16x2(acc[mt][nt][0] * s0, acc[mt][nt][1] * s0);
                if (r1 < n)
                    *(unsigned int*)&Pb[(size_t)r1 * CD + cn] =
                        pack_bf16x2(acc[mt][nt][2] * s1, acc[mt][nt][3] * s1);
            }
        }
    }
}

// ---------------- gather (bf16 in, fp32 accum, bf16 out) ----------------------------
// H[i] = bf16(relu(dis[i]*(P[i] + sum_{j->i} P[j]) + b)); one warp/node, uint2=4 bf16/lane
__global__ void k_gather(const float* __restrict__ bias, int n) {
    int w = (blockIdx.x * blockDim.x + threadIdx.x) >> 5;
    if (w >= n) return;
    int lane = threadIdx.x & 31;

    const uint2* __restrict__ P2 = (const uint2*)g_P;   // bf16 view: 32 uint2 per row
    uint2 sv = P2[(size_t)w * 32 + lane];               // self loop
    float ax = __low2float(*(__nv_bfloat162*)&sv.x);
    float ay = __high2float(*(__nv_bfloat162*)&sv.x);
    float az = __low2float(*(__nv_bfloat162*)&sv.y);
    float aw = __high2float(*(__nv_bfloat162*)&sv.y);

    int o = g_off[w];
    int c = g_cnt[w];
    int j = 0;
    for (; j + 2 <= c; j += 2) {
        int r0 = g_bkt[o + j];
        int r1 = g_bkt[o + j + 1];
        uint2 v0 = P2[(size_t)r0 * 32 + lane];
        uint2 v1 = P2[(size_t)r1 * 32 + lane];
        ax += __low2float(*(__nv_bfloat162*)&v0.x);
        ay += __high2float(*(__nv_bfloat162*)&v0.x);
        az += __low2float(*(__nv_bfloat162*)&v0.y);
        aw += __high2float(*(__nv_bfloat162*)&v0.y);
        ax += __low2float(*(__nv_bfloat162*)&v1.x);
        ay += __high2float(*(__nv_bfloat162*)&v1.x);
        az += __low2float(*(__nv_bfloat162*)&v1.y);
        aw += __high2float(*(__nv_bfloat162*)&v1.y);
    }
    if (j < c) {
        int r0 = g_bkt[o + j];
        uint2 v0 = P2[(size_t)r0 * 32 + lane];
        ax += __low2float(*(__nv_bfloat162*)&v0.x);
        ay += __high2float(*(__nv_bfloat162*)&v0.x);
        az += __low2float(*(__nv_bfloat162*)&v0.y);
        aw += __high2float(*(__nv_bfloat162*)&v0.y);
    }

    float s = g_dis[w];
    float4 b = *(const float4*)&bias[lane * 4];
    float ox = fmaxf(fmaf(ax, s, b.x), 0.0f);
    float oy = fmaxf(fmaf(ay, s, b.y), 0.0f);
    float oz = fmaxf(fmaf(az, s, b.z), 0.0f);
    float ow = fmaxf(fmaf(aw, s, b.w), 0.0f);
    uint2 out = make_uint2(pack_bf16x2(ox, oy), pack_bf16x2(oz, ow));
    ((uint2*)g_H)[(size_t)w * 32 + lane] = out;
}

// ---------------- log_softmax (fp32) ----------------
__global__ void k_logsoftmax(const float* __restrict__ bl, float* __restrict__ out, int n) {
    int w = (blockIdx.x * blockDim.x + threadIdx.x) >> 5;
    if (w >= n) return;
    int lane = threadIdx.x & 31;

    float4 v = *(const float4*)&g_P[(size_t)w * CD + lane * 4];
    float4 b = *(const float4*)&bl[lane * 4];
    v.x += b.x; v.y += b.y; v.z += b.z; v.w += b.w;

    float m = fmaxf(fmaxf(v.x, v.y), fmaxf(v.z, v.w));
#pragma unroll
    for (int d = 16; d; d >>= 1) m = fmaxf(m, __shfl_xor_sync(0xFFFFFFFFu, m, d));

    float s = expf(v.x - m) + expf(v.y - m) + expf(v.z - m) + expf(v.w - m);
#pragma unroll
    for (int d = 16; d; d >>= 1) s += __shfl_xor_sync(0xFFFFFFFFu, s, d);

    float l = m + logf(s);
    float4 o = make_float4(v.x - l, v.y - l, v.z - l, v.w - l);
    *(float4*)&out[(size_t)w * CD + lane * 4] = o;
}

// ---------------- launch ----------------
extern "C" void kernel_launch(void* const* d_in, const int* in_sizes, int n_in,
                              void* d_out, int out_size) {
    const float* x  = (const float*)d_in[0];
    const int*   ei = (const int*)d_in[1];
    const float* W1 = (const float*)d_in[2];
    const float* b1 = (const float*)d_in[3];
    const float* W2 = (const float*)d_in[4];
    const float* b2 = (const float*)d_in[5];
    const float* Wl = (const float*)d_in[6];
    const float* bl = (const float*)d_in[7];

    int n = in_sizes[0] / CD;
    int E = in_sizes[1] / 2;
    const int* row = ei;
    const int* col = ei + E;

    int nb256 = (n + 255) / 256;
    int nbScan = (n + 1023) / 1024;
    int gatherB = (n + 7) / 8;
    int gemmB = (n + 127) / 128;

    // degree + bucketing
    k_zero_cnt<<<nb256, 256>>>(n);
    k_count<<<2048, 256>>>(col, E);
    k_dis<<<nb256, 256>>>(n);
    k_scan1<<<nbScan, 1024>>>(n);
    k_scan2<<<1, 128>>>(nbScan);
    k_scan3<<<nb256, 256>>>(n);
    k_fill<<<2048, 256>>>(row, col, E);

    // conv1
    k_cvtW<<<64, 256>>>(W1);
    k_gemm_bf16<<<gemmB, 256>>>(x, 1, 1, 0, n);
    k_gather<<<gatherB, 256>>>(b1, n);

    // conv2
    k_cvtW<<<64, 256>>>(W2);
    k_gemm_bf16<<<gemmB, 256>>>(nullptr, 0, 1, 0, n);
    k_gather<<<gatherB, 256>>>(b2, n);

    // linear + log_softmax
    k_cvtW<<<64, 256>>>(Wl);
    k_gemm_bf16<<<gemmB, 256>>>(nullptr, 0, 0, 1, n);
    k_logsoftmax<<<gatherB, 256>>>(bl, (float*)d_out, n);
}